// round 15
// baseline (speedup 1.0000x reference)
#include <cuda_runtime.h>
#include <cuda_bf16.h>
#include <cstdint>

// ---------------------------------------------------------------------------
// MultiHeadAttentionBlock — softmax DISCARDED => fully linear. Algebraic fold:
//   X2_b = v_b^T k_b   (NT, K=2048, split-K=2)
//   Z partials -> mfold directly ;  M = (1/8)[(Z Wv^T)[hblk] + rank-1 terms]
//   WT fold (fused M-reduce) ; b' = bq WT^T + bo (side stream, || G GEMM)
//   G_b = WT_b @ Wq (split-K=2) ;  out_b = q_b @ G_b^T + b'
// GEMMs: bf16 hi/lo split (3 MMAs) mma.sync (~288 TF/s ceiling on sm_103).
// R15 = R14 winner (342.2us) + colsum occupancy fix (SCH 64) + fine-grained
// per-dependency join events.
// ---------------------------------------------------------------------------

#define Bsz 2
#define Ssz 2048
#define Dsz 1024
#define Hsz 16
#define DKsz 64
#define SCH 64          // S-chunks for colsum (32 rows each)

#define NELEM (Bsz * Ssz * Dsz)
#define WELEM (Dsz * Dsz)
#define BDD   (Bsz * Dsz * Dsz)
#define MELEM (Bsz * Hsz * DKsz * DKsz)

__device__ __nv_bfloat16 g_qh[NELEM], g_ql[NELEM];
__device__ __nv_bfloat16 g_kTh[NELEM], g_kTl[NELEM];     // [B][D][S]
__device__ __nv_bfloat16 g_vTh[NELEM], g_vTl[NELEM];     // [B][D][S]
__device__ __nv_bfloat16 g_wkh[WELEM], g_wkl[WELEM];
__device__ __nv_bfloat16 g_wqTh[WELEM], g_wqTl[WELEM];   // Wq^T [d][o]
__device__ __nv_bfloat16 g_Xh[BDD], g_Xl[BDD];           // X2
__device__ float g_part[4 * WELEM];                      // split-K partials
__device__ float g_skpart[SCH * Bsz * Dsz], g_svpart[SCH * Bsz * Dsz];
__device__ float g_sk[Bsz * Dsz], g_sv[Bsz * Dsz];
__device__ float g_wksk[Bsz * Dsz], g_wvsv[Bsz * Dsz];
__device__ float g_Mpart[4 * MELEM];
__device__ __nv_bfloat16 g_WTh[BDD], g_WTl[BDD];
__device__ __nv_bfloat16 g_Gh[BDD], g_Gl[BDD];
__device__ float g_bp[Bsz * Dsz];

// ---------------------------------------------------------------------------
__device__ __forceinline__ void ldsm4(unsigned r[4], const __nv_bfloat16* p) {
    unsigned a = (unsigned)__cvta_generic_to_shared(p);
    asm volatile("ldmatrix.sync.aligned.m8n8.x4.shared.b16 {%0,%1,%2,%3}, [%4];\n"
                 : "=r"(r[0]), "=r"(r[1]), "=r"(r[2]), "=r"(r[3]) : "r"(a));
}
__device__ __forceinline__ void mma_bf16(float c[4], const unsigned a[4], const unsigned b[2]) {
    asm volatile("mma.sync.aligned.m16n8k16.row.col.f32.bf16.bf16.f32 "
                 "{%0,%1,%2,%3}, {%4,%5,%6,%7}, {%8,%9}, {%0,%1,%2,%3};\n"
                 : "+f"(c[0]), "+f"(c[1]), "+f"(c[2]), "+f"(c[3])
                 : "r"(a[0]), "r"(a[1]), "r"(a[2]), "r"(a[3]), "r"(b[0]), "r"(b[1]));
}
__device__ __forceinline__ void cpa16(void* dst, const void* src) {
    unsigned d = (unsigned)__cvta_generic_to_shared(dst);
    asm volatile("cp.async.cg.shared.global [%0], [%1], 16;\n" :: "r"(d), "l"(src));
}
__device__ __forceinline__ void cpa_commit() { asm volatile("cp.async.commit_group;\n"); }
__device__ __forceinline__ void cpa_wait1()  { asm volatile("cp.async.wait_group 1;\n"); }
__device__ __forceinline__ void cpa_wait0()  { asm volatile("cp.async.wait_group 0;\n"); }

// ---------------------------------------------------------------------------
__global__ __launch_bounds__(256)
void split_kernel(const float* __restrict__ x, __nv_bfloat16* __restrict__ xh,
                  __nv_bfloat16* __restrict__ xl, int n4)
{
    const int i = blockIdx.x * 256 + threadIdx.x;
    if (i >= n4) return;
    float4 v = ((const float4*)x)[i];
    __nv_bfloat16 h0 = __float2bfloat16_rn(v.x), h1 = __float2bfloat16_rn(v.y);
    __nv_bfloat16 h2 = __float2bfloat16_rn(v.z), h3 = __float2bfloat16_rn(v.w);
    ((__nv_bfloat162*)xh)[2 * i]     = __halves2bfloat162(h0, h1);
    ((__nv_bfloat162*)xh)[2 * i + 1] = __halves2bfloat162(h2, h3);
    ((__nv_bfloat162*)xl)[2 * i]     = __halves2bfloat162(
        __float2bfloat16_rn(v.x - __bfloat162float(h0)),
        __float2bfloat16_rn(v.y - __bfloat162float(h1)));
    ((__nv_bfloat162*)xl)[2 * i + 1] = __halves2bfloat162(
        __float2bfloat16_rn(v.z - __bfloat162float(h2)),
        __float2bfloat16_rn(v.w - __bfloat162float(h3)));
}

__global__ __launch_bounds__(256)
void tsplit_kernel(const float* __restrict__ X, __nv_bfloat16* __restrict__ Th,
                   __nv_bfloat16* __restrict__ Tl, int R, int C)
{
    __shared__ float sm[32][33];
    const int c0 = blockIdx.x * 32, r0 = blockIdx.y * 32;
    const long z = (long)blockIdx.z * R * C;
    const int tx = threadIdx.x & 31, ty = threadIdx.x >> 5;
    #pragma unroll
    for (int i = 0; i < 4; i++)
        sm[ty + i * 8][tx] = X[z + (long)(r0 + ty + i * 8) * C + c0 + tx];
    __syncthreads();
    #pragma unroll
    for (int i = 0; i < 4; i++) {
        const float v = sm[tx][ty + i * 8];
        const __nv_bfloat16 h = __float2bfloat16_rn(v);
        const long o = z + (long)(c0 + ty + i * 8) * R + r0 + tx;
        Th[o] = h;
        Tl[o] = __float2bfloat16_rn(v - __bfloat162float(h));
    }
}

__global__ __launch_bounds__(256)
void tsplitKV(const float* __restrict__ Kx, const float* __restrict__ Vx,
              __nv_bfloat16* __restrict__ kTh, __nv_bfloat16* __restrict__ kTl,
              __nv_bfloat16* __restrict__ vTh, __nv_bfloat16* __restrict__ vTl)
{
    __shared__ float smk[32][33];
    __shared__ float smv[32][33];
    const int c0 = blockIdx.x * 32, r0 = blockIdx.y * 32;
    const long z = (long)blockIdx.z * Ssz * Dsz;
    const int tx = threadIdx.x & 31, ty = threadIdx.x >> 5;
    #pragma unroll
    for (int i = 0; i < 4; i++) {
        const long gi = z + (long)(r0 + ty + i * 8) * Dsz + c0 + tx;
        smk[ty + i * 8][tx] = Kx[gi];
        smv[ty + i * 8][tx] = Vx[gi];
    }
    __syncthreads();
    #pragma unroll
    for (int i = 0; i < 4; i++) {
        const long o = z + (long)(c0 + ty + i * 8) * Ssz + r0 + tx;
        float a = smk[tx][ty + i * 8];
        __nv_bfloat16 h = __float2bfloat16_rn(a);
        kTh[o] = h;
        kTl[o] = __float2bfloat16_rn(a - __bfloat162float(h));
        float b = smv[tx][ty + i * 8];
        __nv_bfloat16 g = __float2bfloat16_rn(b);
        vTh[o] = g;
        vTl[o] = __float2bfloat16_rn(b - __bfloat162float(g));
    }
}

// Column-sum partials: grid (D/256, SCH, B); each CTA sums 32 rows.
__global__ __launch_bounds__(256)
void colsum_part(const float* __restrict__ k, const float* __restrict__ v,
                 float* __restrict__ skp, float* __restrict__ svp)
{
    const int d = blockIdx.x * 256 + threadIdx.x;
    const int ch = blockIdx.y, b = blockIdx.z;
    const long base = (long)b * Ssz * Dsz + (long)(ch * (Ssz / SCH)) * Dsz + d;
    float a = 0.f, c = 0.f;
    #pragma unroll 4
    for (int s = 0; s < Ssz / SCH; s++) {
        a += k[base + (long)s * Dsz];
        c += v[base + (long)s * Dsz];
    }
    skp[((long)ch * Bsz + b) * Dsz + d] = a;
    svp[((long)ch * Bsz + b) * Dsz + d] = c;
}

__global__ __launch_bounds__(256)
void colsum_reduce(const float* __restrict__ skp, const float* __restrict__ svp,
                   float* __restrict__ sk, float* __restrict__ sv)
{
    const int i = blockIdx.x * 256 + threadIdx.x;
    float a = 0.f, c = 0.f;
    #pragma unroll 8
    for (int ch = 0; ch < SCH; ch++) {
        a += skp[(long)ch * Bsz * Dsz + i];
        c += svp[(long)ch * Bsz * Dsz + i];
    }
    sk[i] = a; sv[i] = c;
}

__global__ __launch_bounds__(128)
void matvec_kernel(const float* __restrict__ wk, const float* __restrict__ wv,
                   const float* __restrict__ sk, const float* __restrict__ sv,
                   float* __restrict__ wksk, float* __restrict__ wvsv)
{
    const int o = blockIdx.x, which = blockIdx.y, b = blockIdx.z;
    const float* W = which ? wv : wk;
    const float* s = (which ? sv : sk) + b * Dsz;
    float p = 0.f;
    for (int d = threadIdx.x; d < Dsz; d += 128) p += W[(long)o * Dsz + d] * s[d];
    #pragma unroll
    for (int off = 16; off; off >>= 1) p += __shfl_down_sync(0xffffffff, p, off);
    __shared__ float red[4];
    if ((threadIdx.x & 31) == 0) red[threadIdx.x >> 5] = p;
    __syncthreads();
    if (threadIdx.x == 0)
        (which ? wvsv : wksk)[b * Dsz + o] = red[0] + red[1] + red[2] + red[3];
}

// ---------------------------------------------------------------------------
#define PITCH 40
#define ARR_H (128 * PITCH)
#define STAGE_H (4 * ARR_H)
#define GSMEM (2 * STAGE_H * 2)

// Split-K GEMM: fp32 partials. grid (N/128, M/128, nbatch*2), z2 = 2z+kc.
__global__ __launch_bounds__(128)
void gemm_sk(const __nv_bfloat16* __restrict__ Agh, const __nv_bfloat16* __restrict__ Agl,
             const __nv_bfloat16* __restrict__ Bgh, const __nv_bfloat16* __restrict__ Bgl,
             float* __restrict__ Cp, int N, int Kc, int ldk, long sA, long sB)
{
    extern __shared__ __align__(16) __nv_bfloat16 smem[];
    const int z2 = blockIdx.z, z = z2 >> 1, kc = z2 & 1;
    const __nv_bfloat16* Azh = Agh + (long)z * sA + (long)kc * Kc;
    const __nv_bfloat16* Azl = Agl + (long)z * sA + (long)kc * Kc;
    const __nv_bfloat16* Bzh = Bgh + (long)z * sB + (long)kc * Kc;
    const __nv_bfloat16* Bzl = Bgl + (long)z * sB + (long)kc * Kc;
    const int bm = blockIdx.y * 128, bn = blockIdx.x * 128;
    const int tid = threadIdx.x, lane = tid & 31, warp = tid >> 5;
    const int wm = warp >> 1, wn = warp & 1;

    float acc[4][8][4];
    #pragma unroll
    for (int mt = 0; mt < 4; mt++)
        #pragma unroll
        for (int nt = 0; nt < 8; nt++)
            #pragma unroll
            for (int e = 0; e < 4; e++) acc[mt][nt][e] = 0.f;

    auto load_stage = [&](int buf, int k0) {
        __nv_bfloat16* S = smem + buf * STAGE_H;
        #pragma unroll
        for (int it = 0; it < 4; it++) {
            const int idx = tid + it * 128;
            const int r = idx >> 2, c = (idx & 3) * 8;
            const long ga = (long)(bm + r) * ldk + k0 + c;
            const long gb = (long)(bn + r) * ldk + k0 + c;
            __nv_bfloat16* row = S + r * PITCH + c;
            cpa16(row,             Azh + ga);
            cpa16(row + ARR_H,     Azl + ga);
            cpa16(row + 2 * ARR_H, Bzh + gb);
            cpa16(row + 3 * ARR_H, Bzl + gb);
        }
        cpa_commit();
    };

    load_stage(0, 0);
    load_stage(1, 32);

    const int NS = Kc / 32;
    for (int i = 0; i < NS; i++) {
        if (i == NS - 1) cpa_wait0(); else cpa_wait1();
        __syncthreads();

        const __nv_bfloat16* S = smem + (i & 1) * STAGE_H;
        const __nv_bfloat16* sAh = S;
        const __nv_bfloat16* sAl = S + ARR_H;
        const __nv_bfloat16* sBh = S + 2 * ARR_H;
        const __nv_bfloat16* sBl = S + 3 * ARR_H;

        #pragma unroll
        for (int kk = 0; kk < 32; kk += 16) {
            unsigned aH[4][4], aL[4][4];
            const int arow = wm * 64 + (lane & 15);
            const int acol = kk + (lane >> 4) * 8;
            #pragma unroll
            for (int mt = 0; mt < 4; mt++) {
                ldsm4(aH[mt], sAh + (arow + mt * 16) * PITCH + acol);
                ldsm4(aL[mt], sAl + (arow + mt * 16) * PITCH + acol);
            }
            const int g = lane >> 3;
            #pragma unroll
            for (int half = 0; half < 2; half++) {
                unsigned bH[4][2], bL[4][2];
                #pragma unroll
                for (int p = 0; p < 2; p++) {
                    const int brow = wn * 64 + half * 32 + p * 16 + ((g >> 1) << 3) + (lane & 7);
                    const int bcol = kk + (g & 1) * 8;
                    unsigned tt[4];
                    ldsm4(tt, sBh + brow * PITCH + bcol);
                    bH[2 * p][0] = tt[0]; bH[2 * p][1] = tt[1];
                    bH[2 * p + 1][0] = tt[2]; bH[2 * p + 1][1] = tt[3];
                    ldsm4(tt, sBl + brow * PITCH + bcol);
                    bL[2 * p][0] = tt[0]; bL[2 * p][1] = tt[1];
                    bL[2 * p + 1][0] = tt[2]; bL[2 * p + 1][1] = tt[3];
                }
                #pragma unroll
                for (int mt = 0; mt < 4; mt++)
                    #pragma unroll
                    for (int nn = 0; nn < 4; nn++) {
                        const int nt = half * 4 + nn;
                        mma_bf16(acc[mt][nt], aH[mt], bH[nn]);
                        mma_bf16(acc[mt][nt], aH[mt], bL[nn]);
                        mma_bf16(acc[mt][nt], aL[mt], bH[nn]);
                    }
            }
        }
        __syncthreads();
        if (i + 2 < NS) load_stage(i & 1, (i + 2) * 32);
    }

    float* Cz = Cp + (long)z2 * WELEM;
    const int crow = bm + wm * 64 + lane / 4;
    const int ccol0 = bn + wn * 64 + (lane % 4) * 2;
    #pragma unroll
    for (int mt = 0; mt < 4; mt++) {
        #pragma unroll
        for (int nt = 0; nt < 8; nt++) {
            const int col = ccol0 + nt * 8;
            const int r0 = crow + mt * 16;
            *(float2*)(Cz + (long)r0 * N + col) = make_float2(acc[mt][nt][0], acc[mt][nt][1]);
            *(float2*)(Cz + (long)(r0 + 8) * N + col) = make_float2(acc[mt][nt][2], acc[mt][nt][3]);
        }
    }
}

// Reduce split-K partials -> bf16 hi/lo
__global__ __launch_bounds__(256)
void sk_red_hl(const float* __restrict__ Cp, __nv_bfloat16* __restrict__ xh,
               __nv_bfloat16* __restrict__ xl)
{
    const int i = blockIdx.x * 256 + threadIdx.x;
    const int b = blockIdx.y;
    const float4 p0 = ((const float4*)(Cp + (long)(2 * b) * WELEM))[i];
    const float4 p1 = ((const float4*)(Cp + (long)(2 * b + 1) * WELEM))[i];
    const float s0 = p0.x + p1.x, s1 = p0.y + p1.y, s2 = p0.z + p1.z, s3 = p0.w + p1.w;
    __nv_bfloat16 h0 = __float2bfloat16_rn(s0), h1 = __float2bfloat16_rn(s1);
    __nv_bfloat16 h2 = __float2bfloat16_rn(s2), h3 = __float2bfloat16_rn(s3);
    const long o = (long)b * WELEM / 4 + i;
    ((__nv_bfloat162*)xh)[2 * o]     = __halves2bfloat162(h0, h1);
    ((__nv_bfloat162*)xh)[2 * o + 1] = __halves2bfloat162(h2, h3);
    ((__nv_bfloat162*)xl)[2 * o]     = __halves2bfloat162(
        __float2bfloat16_rn(s0 - __bfloat162float(h0)),
        __float2bfloat16_rn(s1 - __bfloat162float(h1)));
    ((__nv_bfloat162*)xl)[2 * o + 1] = __halves2bfloat162(
        __float2bfloat16_rn(s2 - __bfloat162float(h2)),
        __float2bfloat16_rn(s3 - __bfloat162float(h3)));
}

// ---------------------------------------------------------------------------
// Full-K GEMM with bias, fp32 out: grid (N/128, M/128, B)
// ---------------------------------------------------------------------------
__global__ __launch_bounds__(128)
void gemm_mma(const __nv_bfloat16* __restrict__ Agh, const __nv_bfloat16* __restrict__ Agl,
              const __nv_bfloat16* __restrict__ Bgh, const __nv_bfloat16* __restrict__ Bgl,
              const float* __restrict__ bias, float* __restrict__ Cf,
              int N, int K, long sA, long sB, long sC, long sBias)
{
    extern __shared__ __align__(16) __nv_bfloat16 smem[];
    const __nv_bfloat16* Azh = Agh + (long)blockIdx.z * sA;
    const __nv_bfloat16* Azl = Agl + (long)blockIdx.z * sA;
    const __nv_bfloat16* Bzh = Bgh + (long)blockIdx.z * sB;
    const __nv_bfloat16* Bzl = Bgl + (long)blockIdx.z * sB;
    const float* bz = bias + (long)blockIdx.z * sBias;
    const int bm = blockIdx.y * 128, bn = blockIdx.x * 128;
    const int tid = threadIdx.x, lane = tid & 31, warp = tid >> 5;
    const int wm = warp >> 1, wn = warp & 1;

    float acc[4][8][4];
    #pragma unroll
    for (int mt = 0; mt < 4; mt++)
        #pragma unroll
        for (int nt = 0; nt < 8; nt++)
            #pragma unroll
            for (int e = 0; e < 4; e++) acc[mt][nt][e] = 0.f;

    auto load_stage = [&](int buf, int k0) {
        __nv_bfloat16* S = smem + buf * STAGE_H;
        #pragma unroll
        for (int it = 0; it < 4; it++) {
            const int idx = tid + it * 128;
            const int r = idx >> 2, c = (idx & 3) * 8;
            const long ga = (long)(bm + r) * K + k0 + c;
            const long gb = (long)(bn + r) * K + k0 + c;
            __nv_bfloat16* row = S + r * PITCH + c;
            cpa16(row,             Azh + ga);
            cpa16(row + ARR_H,     Azl + ga);
            cpa16(row + 2 * ARR_H, Bzh + gb);
            cpa16(row + 3 * ARR_H, Bzl + gb);
        }
        cpa_commit();
    };

    load_stage(0, 0);
    load_stage(1, 32);

    const int NS = K / 32;
    for (int i = 0; i < NS; i++) {
        if (i == NS - 1) cpa_wait0(); else cpa_wait1();
        __syncthreads();

        const __nv_bfloat16* S = smem + (i & 1) * STAGE_H;
        const __nv_bfloat16* sAh = S;
        const __nv_bfloat16* sAl = S + ARR_H;
        const __nv_bfloat16* sBh = S + 2 * ARR_H;
        const __nv_bfloat16* sBl = S + 3 * ARR_H;

        #pragma unroll
        for (int kk = 0; kk < 32; kk += 16) {
            unsigned aH[4][4], aL[4][4];
            const int arow = wm * 64 + (lane & 15);
            const int acol = kk + (lane >> 4) * 8;
            #pragma unroll
            for (int mt = 0; mt < 4; mt++) {
                ldsm4(aH[mt], sAh + (arow + mt * 16) * PITCH + acol);
                ldsm4(aL[mt], sAl + (arow + mt * 16) * PITCH + acol);
            }
            const int g = lane >> 3;
            #pragma unroll
            for (int half = 0; half < 2; half++) {
                unsigned bH[4][2], bL[4][2];
                #pragma unroll
                for (int p = 0; p < 2; p++) {
                    const int brow = wn * 64 + half * 32 + p * 16 + ((g >> 1) << 3) + (lane & 7);
                    const int bcol = kk + (g & 1) * 8;
                    unsigned tt[4];
                    ldsm4(tt, sBh + brow * PITCH + bcol);
                    bH[2 * p][0] = tt[0]; bH[2 * p][1] = tt[1];
                    bH[2 * p + 1][0] = tt[2]; bH[2 * p + 1][1] = tt[3];
                    ldsm4(tt, sBl + brow * PITCH + bcol);
                    bL[2 * p][0] = tt[0]; bL[2 * p][1] = tt[1];
                    bL[2 * p + 1][0] = tt[2]; bL[2 * p + 1][1] = tt[3];
                }
                #pragma unroll
                for (int mt = 0; mt < 4; mt++)
                    #pragma unroll
                    for (int nn = 0; nn < 4; nn++) {
                        const int nt = half * 4 + nn;
                        mma_bf16(acc[mt][nt], aH[mt], bH[nn]);
                        mma_bf16(acc[mt][nt], aH[mt], bL[nn]);
                        mma_bf16(acc[mt][nt], aL[mt], bH[nn]);
                    }
            }
        }
        __syncthreads();
        if (i + 2 < NS) load_stage(i & 1, (i + 2) * 32);
    }

    float* Cz = Cf + (long)blockIdx.z * sC;
    const int crow = bm + wm * 64 + lane / 4;
    const int ccol0 = bn + wn * 64 + (lane % 4) * 2;
    #pragma unroll
    for (int mt = 0; mt < 4; mt++) {
        #pragma unroll
        for (int nt = 0; nt < 8; nt++) {
            const int col = ccol0 + nt * 8;
            const float2 bb = *(const float2*)(bz + col);
            const int r0 = crow + mt * 16;
            *(float2*)(Cz + (long)r0 * N + col) =
                make_float2(acc[mt][nt][0] + bb.x, acc[mt][nt][1] + bb.y);
            *(float2*)(Cz + (long)(r0 + 8) * N + col) =
                make_float2(acc[mt][nt][2] + bb.x, acc[mt][nt][3] + bb.y);
        }
    }
}

// ---------------------------------------------------------------------------
// mfold_part: reads Z split-K partials directly (Z = part[2b] + part[2b+1])
__global__ __launch_bounds__(256)
void mfold_part(const float* __restrict__ Cp, const float* __restrict__ wv,
                float* __restrict__ part)
{
    __shared__ float Zs[64][33];
    __shared__ float Ws[64][33];
    const int bh = blockIdx.x;
    const int b = bh >> 4, h = bh & 15;
    const int chunk = blockIdx.y;
    const int tid = threadIdx.x;
    const int ti = (tid >> 4) * 4, tj = (tid & 15) * 4;
    const float* Z0 = Cp + (long)(2 * b) * WELEM + (long)(h * DKsz) * Dsz;
    const float* Z1 = Cp + (long)(2 * b + 1) * WELEM + (long)(h * DKsz) * Dsz;
    const long wbase = (long)(h * DKsz) * Dsz;

    float acc[4][4] = {};
    for (int e0 = chunk * 256; e0 < chunk * 256 + 256; e0 += 32) {
        #pragma unroll
        for (int it = 0; it < 2; it++) {
            const int s = tid + it * 256;
            const int row = s >> 3, c4 = (s & 7) * 4;
            float4 z0 = *(const float4*)(Z0 + (long)row * Dsz + e0 + c4);
            float4 z1 = *(const float4*)(Z1 + (long)row * Dsz + e0 + c4);
            Zs[row][c4]   = z0.x + z1.x; Zs[row][c4+1] = z0.y + z1.y;
            Zs[row][c4+2] = z0.z + z1.z; Zs[row][c4+3] = z0.w + z1.w;
            float4 wvv = *(const float4*)(wv + wbase + (long)row * Dsz + e0 + c4);
            Ws[row][c4] = wvv.x; Ws[row][c4+1] = wvv.y; Ws[row][c4+2] = wvv.z; Ws[row][c4+3] = wvv.w;
        }
        __syncthreads();
        #pragma unroll
        for (int ee = 0; ee < 32; ee++) {
            float a[4], w[4];
            #pragma unroll
            for (int u = 0; u < 4; u++) { a[u] = Zs[ti + u][ee]; w[u] = Ws[tj + u][ee]; }
            #pragma unroll
            for (int i = 0; i < 4; i++)
                #pragma unroll
                for (int j = 0; j < 4; j++) acc[i][j] += a[i] * w[j];
        }
        __syncthreads();
    }
    float* outp = part + (long)chunk * MELEM + (long)bh * (DKsz * DKsz);
    #pragma unroll
    for (int i = 0; i < 4; i++)
        #pragma unroll
        for (int j = 0; j < 4; j++)
            outp[(ti + i) * DKsz + tj + j] = acc[i][j];
}

// wcomb with fused M-reduction: M built in smem from 4 Mpart chunks + bias terms.
__global__ __launch_bounds__(256)
void wcomb_kernel(const float* __restrict__ Mpart, const float* __restrict__ Wo,
                  const float* __restrict__ wksk, const float* __restrict__ wvsv,
                  const float* __restrict__ bk, const float* __restrict__ bv,
                  __nv_bfloat16* __restrict__ WTh, __nv_bfloat16* __restrict__ WTl)
{
    __shared__ float MshT[64 * 64];   // [j][i]
    __shared__ float WoSh[32][64];
    const int c0 = blockIdx.x * 32;
    const int h = blockIdx.y, b = blockIdx.z;
    const int tid = threadIdx.x;
    const long mbase = (long)(b * Hsz + h) * (DKsz * DKsz);

    for (int t = tid; t < 4096; t += 256) {
        const int i = t >> 6, j = t & 63;
        float s = 0.f;
        #pragma unroll
        for (int c = 0; c < 4; c++) s += Mpart[(long)c * MELEM + mbase + t];
        const int oi = h * DKsz + i, oj = h * DKsz + j;
        s += wksk[b * Dsz + oi] * bv[oj]
           + bk[oi] * wvsv[b * Dsz + oj]
           + (float)Ssz * bk[oi] * bv[oj];
        MshT[j * 64 + i] = s * 0.125f;
    }
    for (int t = tid; t < 2048; t += 256) {
        const int cc = t >> 6, j = t & 63;
        WoSh[cc][j] = Wo[(size_t)(c0 + cc) * Dsz + h * DKsz + j];
    }
    __syncthreads();

    const int cc = tid >> 3;
    const int i0 = (tid & 7) * 8;
    float acc[8] = {};
    #pragma unroll
    for (int j = 0; j < 64; j++) {
        const float w = WoSh[cc][j];
        #pragma unroll
        for (int u = 0; u < 8; u++) acc[u] += w * MshT[j * 64 + i0 + u];
    }
    const long off = (long)(b * Dsz + c0 + cc) * Dsz + h * DKsz + i0;
    #pragma unroll
    for (int u = 0; u < 8; u += 2) {
        __nv_bfloat16 h0 = __float2bfloat16_rn(acc[u]);
        __nv_bfloat16 h1 = __float2bfloat16_rn(acc[u + 1]);
        *(__nv_bfloat162*)(WTh + off + u) = __halves2bfloat162(h0, h1);
        *(__nv_bfloat162*)(WTl + off + u) = __halves2bfloat162(
            __float2bfloat16_rn(acc[u] - __bfloat162float(h0)),
            __float2bfloat16_rn(acc[u + 1] - __bfloat162float(h1)));
    }
}

__global__ __launch_bounds__(128)
void bprime_kernel(const __nv_bfloat16* __restrict__ WTh, const __nv_bfloat16* __restrict__ WTl,
                   const float* __restrict__ bq, const float* __restrict__ bo,
                   float* __restrict__ bp)
{
    const int c = blockIdx.x, b = blockIdx.y;
    const long base = (long)b * Dsz * Dsz + (long)c * Dsz;
    float p = 0.f;
    for (int o = threadIdx.x; o < Dsz; o += 128)
        p += bq[o] * (__bfloat162float(WTh[base + o]) + __bfloat162float(WTl[base + o]));
    #pragma unroll
    for (int off = 16; off; off >>= 1) p += __shfl_down_sync(0xffffffff, p, off);
    __shared__ float red[4];
    if ((threadIdx.x & 31) == 0) red[threadIdx.x >> 5] = p;
    __syncthreads();
    if (threadIdx.x == 0)
        bp[b * Dsz + c] = red[0] + red[1] + red[2] + red[3] + bo[c];
}

// ---------------------------------------------------------------------------
extern "C" void kernel_launch(void* const* d_in, const int* in_sizes, int n_in,
                              void* d_out, int out_size)
{
    const float* q  = (const float*)d_in[0];
    const float* k  = (const float*)d_in[1];
    const float* v  = (const float*)d_in[2];
    const float* wq = (const float*)d_in[3];
    const float* bq = (const float*)d_in[4];
    const float* wk = (const float*)d_in[5];
    const float* bk = (const float*)d_in[6];
    const float* wv = (const float*)d_in[7];
    const float* bv = (const float*)d_in[8];
    const float* wo = (const float*)d_in[9];
    const float* bo = (const float*)d_in[10];
    float* out = (float*)d_out;

    __nv_bfloat16 *qh, *ql, *kTh, *kTl, *vTh, *vTl, *wkh, *wkl, *wqTh, *wqTl;
    __nv_bfloat16 *Xh, *Xl, *WTh, *WTl, *Gh, *Gl;
    float *part, *skp, *svp, *sk, *sv, *wksk, *wvsv, *Mp, *bp;
    cudaGetSymbolAddress((void**)&qh, g_qh);     cudaGetSymbolAddress((void**)&ql, g_ql);
    cudaGetSymbolAddress((void**)&kTh, g_kTh);   cudaGetSymbolAddress((void**)&kTl, g_kTl);
    cudaGetSymbolAddress((void**)&vTh, g_vTh);   cudaGetSymbolAddress((void**)&vTl, g_vTl);
    cudaGetSymbolAddress((void**)&wkh, g_wkh);   cudaGetSymbolAddress((void**)&wkl, g_wkl);
    cudaGetSymbolAddress((void**)&wqTh, g_wqTh); cudaGetSymbolAddress((void**)&wqTl, g_wqTl);
    cudaGetSymbolAddress((void**)&Xh, g_Xh);     cudaGetSymbolAddress((void**)&Xl, g_Xl);
    cudaGetSymbolAddress((void**)&part, g_part);
    cudaGetSymbolAddress((void**)&skp, g_skpart); cudaGetSymbolAddress((void**)&svp, g_svpart);
    cudaGetSymbolAddress((void**)&sk, g_sk);     cudaGetSymbolAddress((void**)&sv, g_sv);
    cudaGetSymbolAddress((void**)&wksk, g_wksk); cudaGetSymbolAddress((void**)&wvsv, g_wvsv);
    cudaGetSymbolAddress((void**)&Mp, g_Mpart);
    cudaGetSymbolAddress((void**)&WTh, g_WTh);   cudaGetSymbolAddress((void**)&WTl, g_WTl);
    cudaGetSymbolAddress((void**)&Gh, g_Gh);     cudaGetSymbolAddress((void**)&Gl, g_Gl);
    cudaGetSymbolAddress((void**)&bp, g_bp);

    static cudaStream_t s1 = nullptr;
    static cudaEvent_t e0 = nullptr, e_wk = nullptr, e_mv = nullptr, e_wq = nullptr,
                       e_q = nullptr, ewt = nullptr, ebp = nullptr;
    static int smem_set = 0;
    if (!smem_set) {
        cudaFuncSetAttribute(gemm_mma, cudaFuncAttributeMaxDynamicSharedMemorySize, GSMEM);
        cudaFuncSetAttribute(gemm_sk, cudaFuncAttributeMaxDynamicSharedMemorySize, GSMEM);
        cudaStreamCreateWithFlags(&s1, cudaStreamNonBlocking);
        cudaEventCreateWithFlags(&e0, cudaEventDisableTiming);
        cudaEventCreateWithFlags(&e_wk, cudaEventDisableTiming);
        cudaEventCreateWithFlags(&e_mv, cudaEventDisableTiming);
        cudaEventCreateWithFlags(&e_wq, cudaEventDisableTiming);
        cudaEventCreateWithFlags(&e_q, cudaEventDisableTiming);
        cudaEventCreateWithFlags(&ewt, cudaEventDisableTiming);
        cudaEventCreateWithFlags(&ebp, cudaEventDisableTiming);
        smem_set = 1;
    }

    // ---- fork FIRST (R12/R14 structure) ----
    cudaEventRecord(e0, 0);
    cudaStreamWaitEvent(s1, e0, 0);
    // ordered by when the main chain needs the result:
    split_kernel<<<WELEM / 4 / 256, 256, 0, s1>>>(wk, wkh, wkl, WELEM / 4);
    cudaEventRecord(e_wk, s1);                                      // -> Z GEMM
    colsum_part<<<dim3(Dsz / 256, SCH, Bsz), 256, 0, s1>>>(k, v, skp, svp);
    colsum_reduce<<<(Bsz * Dsz) / 256, 256, 0, s1>>>(skp, svp, sk, sv);
    matvec_kernel<<<dim3(Dsz, 2, Bsz), 128, 0, s1>>>(wk, wv, sk, sv, wksk, wvsv);
    cudaEventRecord(e_mv, s1);                                      // -> wcomb
    tsplit_kernel<<<dim3(Dsz / 32, Dsz / 32, 1), 256, 0, s1>>>(wq, wqTh, wqTl, Dsz, Dsz);
    cudaEventRecord(e_wq, s1);                                      // -> G GEMM
    split_kernel<<<NELEM / 4 / 256, 256, 0, s1>>>(q, qh, ql, NELEM / 4);
    cudaEventRecord(e_q, s1);                                       // -> out GEMM

    // ---- main chain ----
    tsplitKV<<<dim3(Dsz / 32, Ssz / 32, Bsz), 256>>>(k, v, kTh, kTl, vTh, vTl);

    // 1) X2_b = v_b^T k_b  split-K=2 -> bf16 h/l
    gemm_sk<<<dim3(8, 8, 2 * Bsz), 128, GSMEM>>>(
        vTh, vTl, kTh, kTl, part, Dsz, 1024, Ssz,
        (long)Dsz * Ssz, (long)Dsz * Ssz);
    sk_red_hl<<<dim3(WELEM / 4 / 256, Bsz), 256>>>(part, Xh, Xl);

    // 2) Z_b = Wk @ X2_b^T  (needs wk split only)
    cudaStreamWaitEvent(0, e_wk, 0);
    gemm_sk<<<dim3(8, 8, 2 * Bsz), 128, GSMEM>>>(
        wkh, wkl, Xh, Xl, part, Dsz, 512, Dsz,
        0, (long)Dsz * Dsz);

    // 3) M chunk partials (reads Z partials directly)
    mfold_part<<<dim3(Bsz * Hsz, 4), 256>>>(part, wv, Mp);

    // 4) WT fold (needs matvec results)
    cudaStreamWaitEvent(0, e_mv, 0);
    wcomb_kernel<<<dim3(Dsz / 32, Hsz, Bsz), 256>>>(Mp, wo, wksk, wvsv, bk, bv, WTh, WTl);
    cudaEventRecord(ewt, 0);

    // bprime on side stream, parallel with G GEMM
    cudaStreamWaitEvent(s1, ewt, 0);
    bprime_kernel<<<dim3(Dsz, Bsz), 128, 0, s1>>>(WTh, WTl, bq, bo, bp);
    cudaEventRecord(ebp, s1);

    // 5) G_b = WT_b @ Wq  (needs wq transpose-split)
    cudaStreamWaitEvent(0, e_wq, 0);
    gemm_sk<<<dim3(8, 8, 2 * Bsz), 128, GSMEM>>>(
        WTh, WTl, wqTh, wqTl, part, Dsz, 512, Dsz,
        (long)Dsz * Dsz, 0);
    sk_red_hl<<<dim3(WELEM / 4 / 256, Bsz), 256>>>(part, Gh, Gl);

    // 6) out GEMM (needs q split + bprime)
    cudaStreamWaitEvent(0, e_q, 0);
    cudaStreamWaitEvent(0, ebp, 0);
    gemm_mma<<<dim3(Dsz / 128, Ssz / 128, Bsz), 128, GSMEM>>>(
        qh, ql, Gh, Gl, bp, out,
        Dsz, Dsz, (long)Ssz * Dsz, (long)Dsz * Dsz, (long)Ssz * Dsz, Dsz);
}

// round 16
// speedup vs baseline: 1.0218x; 1.0218x over previous
#include <cuda_runtime.h>
#include <cuda_bf16.h>
#include <cstdint>

// ---------------------------------------------------------------------------
// MultiHeadAttentionBlock — softmax DISCARDED => fully linear. Algebraic fold:
//   X2_b = v_b^T k_b   (NT, K=2048, split-K=2)
//   Z partials -> mfold directly ;  M = (1/8)[(Z Wv^T)[hblk] + rank-1 terms]
//   WT fold (fused M-reduce) ; b' = bq WT^T + bo (side stream, || G GEMM)
//   G_b = WT_b @ Wq (split-K=2) ;  out_b = q_b @ G_b^T + b'
// GEMMs: bf16 hi/lo split (3 MMAs) mma.sync (~288 TF/s ceiling on sm_103).
// R16 = R14 winner (342.2us) with ONLY the colsum occupancy fix (SCH 16->64).
// ---------------------------------------------------------------------------

#define Bsz 2
#define Ssz 2048
#define Dsz 1024
#define Hsz 16
#define DKsz 64
#define SCH 64          // S-chunks for colsum (32 rows each; grid 512)

#define NELEM (Bsz * Ssz * Dsz)
#define WELEM (Dsz * Dsz)
#define BDD   (Bsz * Dsz * Dsz)
#define MELEM (Bsz * Hsz * DKsz * DKsz)

__device__ __nv_bfloat16 g_qh[NELEM], g_ql[NELEM];
__device__ __nv_bfloat16 g_kTh[NELEM], g_kTl[NELEM];     // [B][D][S]
__device__ __nv_bfloat16 g_vTh[NELEM], g_vTl[NELEM];     // [B][D][S]
__device__ __nv_bfloat16 g_wkh[WELEM], g_wkl[WELEM];
__device__ __nv_bfloat16 g_wqTh[WELEM], g_wqTl[WELEM];   // Wq^T [d][o]
__device__ __nv_bfloat16 g_Xh[BDD], g_Xl[BDD];           // X2
__device__ float g_part[4 * WELEM];                      // split-K partials
__device__ float g_skpart[SCH * Bsz * Dsz], g_svpart[SCH * Bsz * Dsz];
__device__ float g_sk[Bsz * Dsz], g_sv[Bsz * Dsz];
__device__ float g_wksk[Bsz * Dsz], g_wvsv[Bsz * Dsz];
__device__ float g_Mpart[4 * MELEM];
__device__ __nv_bfloat16 g_WTh[BDD], g_WTl[BDD];
__device__ __nv_bfloat16 g_Gh[BDD], g_Gl[BDD];
__device__ float g_bp[Bsz * Dsz];

// ---------------------------------------------------------------------------
__device__ __forceinline__ void ldsm4(unsigned r[4], const __nv_bfloat16* p) {
    unsigned a = (unsigned)__cvta_generic_to_shared(p);
    asm volatile("ldmatrix.sync.aligned.m8n8.x4.shared.b16 {%0,%1,%2,%3}, [%4];\n"
                 : "=r"(r[0]), "=r"(r[1]), "=r"(r[2]), "=r"(r[3]) : "r"(a));
}
__device__ __forceinline__ void mma_bf16(float c[4], const unsigned a[4], const unsigned b[2]) {
    asm volatile("mma.sync.aligned.m16n8k16.row.col.f32.bf16.bf16.f32 "
                 "{%0,%1,%2,%3}, {%4,%5,%6,%7}, {%8,%9}, {%0,%1,%2,%3};\n"
                 : "+f"(c[0]), "+f"(c[1]), "+f"(c[2]), "+f"(c[3])
                 : "r"(a[0]), "r"(a[1]), "r"(a[2]), "r"(a[3]), "r"(b[0]), "r"(b[1]));
}
__device__ __forceinline__ void cpa16(void* dst, const void* src) {
    unsigned d = (unsigned)__cvta_generic_to_shared(dst);
    asm volatile("cp.async.cg.shared.global [%0], [%1], 16;\n" :: "r"(d), "l"(src));
}
__device__ __forceinline__ void cpa_commit() { asm volatile("cp.async.commit_group;\n"); }
__device__ __forceinline__ void cpa_wait1()  { asm volatile("cp.async.wait_group 1;\n"); }
__device__ __forceinline__ void cpa_wait0()  { asm volatile("cp.async.wait_group 0;\n"); }

// ---------------------------------------------------------------------------
__global__ __launch_bounds__(256)
void split_kernel(const float* __restrict__ x, __nv_bfloat16* __restrict__ xh,
                  __nv_bfloat16* __restrict__ xl, int n4)
{
    const int i = blockIdx.x * 256 + threadIdx.x;
    if (i >= n4) return;
    float4 v = ((const float4*)x)[i];
    __nv_bfloat16 h0 = __float2bfloat16_rn(v.x), h1 = __float2bfloat16_rn(v.y);
    __nv_bfloat16 h2 = __float2bfloat16_rn(v.z), h3 = __float2bfloat16_rn(v.w);
    ((__nv_bfloat162*)xh)[2 * i]     = __halves2bfloat162(h0, h1);
    ((__nv_bfloat162*)xh)[2 * i + 1] = __halves2bfloat162(h2, h3);
    ((__nv_bfloat162*)xl)[2 * i]     = __halves2bfloat162(
        __float2bfloat16_rn(v.x - __bfloat162float(h0)),
        __float2bfloat16_rn(v.y - __bfloat162float(h1)));
    ((__nv_bfloat162*)xl)[2 * i + 1] = __halves2bfloat162(
        __float2bfloat16_rn(v.z - __bfloat162float(h2)),
        __float2bfloat16_rn(v.w - __bfloat162float(h3)));
}

__global__ __launch_bounds__(256)
void tsplit_kernel(const float* __restrict__ X, __nv_bfloat16* __restrict__ Th,
                   __nv_bfloat16* __restrict__ Tl, int R, int C)
{
    __shared__ float sm[32][33];
    const int c0 = blockIdx.x * 32, r0 = blockIdx.y * 32;
    const long z = (long)blockIdx.z * R * C;
    const int tx = threadIdx.x & 31, ty = threadIdx.x >> 5;
    #pragma unroll
    for (int i = 0; i < 4; i++)
        sm[ty + i * 8][tx] = X[z + (long)(r0 + ty + i * 8) * C + c0 + tx];
    __syncthreads();
    #pragma unroll
    for (int i = 0; i < 4; i++) {
        const float v = sm[tx][ty + i * 8];
        const __nv_bfloat16 h = __float2bfloat16_rn(v);
        const long o = z + (long)(c0 + ty + i * 8) * R + r0 + tx;
        Th[o] = h;
        Tl[o] = __float2bfloat16_rn(v - __bfloat162float(h));
    }
}

__global__ __launch_bounds__(256)
void tsplitKV(const float* __restrict__ Kx, const float* __restrict__ Vx,
              __nv_bfloat16* __restrict__ kTh, __nv_bfloat16* __restrict__ kTl,
              __nv_bfloat16* __restrict__ vTh, __nv_bfloat16* __restrict__ vTl)
{
    __shared__ float smk[32][33];
    __shared__ float smv[32][33];
    const int c0 = blockIdx.x * 32, r0 = blockIdx.y * 32;
    const long z = (long)blockIdx.z * Ssz * Dsz;
    const int tx = threadIdx.x & 31, ty = threadIdx.x >> 5;
    #pragma unroll
    for (int i = 0; i < 4; i++) {
        const long gi = z + (long)(r0 + ty + i * 8) * Dsz + c0 + tx;
        smk[ty + i * 8][tx] = Kx[gi];
        smv[ty + i * 8][tx] = Vx[gi];
    }
    __syncthreads();
    #pragma unroll
    for (int i = 0; i < 4; i++) {
        const long o = z + (long)(c0 + ty + i * 8) * Ssz + r0 + tx;
        float a = smk[tx][ty + i * 8];
        __nv_bfloat16 h = __float2bfloat16_rn(a);
        kTh[o] = h;
        kTl[o] = __float2bfloat16_rn(a - __bfloat162float(h));
        float b = smv[tx][ty + i * 8];
        __nv_bfloat16 g = __float2bfloat16_rn(b);
        vTh[o] = g;
        vTl[o] = __float2bfloat16_rn(b - __bfloat162float(g));
    }
}

// Column-sum partials: grid (D/256, SCH, B); each CTA sums 32 rows.
__global__ __launch_bounds__(256)
void colsum_part(const float* __restrict__ k, const float* __restrict__ v,
                 float* __restrict__ skp, float* __restrict__ svp)
{
    const int d = blockIdx.x * 256 + threadIdx.x;
    const int ch = blockIdx.y, b = blockIdx.z;
    const long base = (long)b * Ssz * Dsz + (long)(ch * (Ssz / SCH)) * Dsz + d;
    float a = 0.f, c = 0.f;
    #pragma unroll 4
    for (int s = 0; s < Ssz / SCH; s++) {
        a += k[base + (long)s * Dsz];
        c += v[base + (long)s * Dsz];
    }
    skp[((long)ch * Bsz + b) * Dsz + d] = a;
    svp[((long)ch * Bsz + b) * Dsz + d] = c;
}

__global__ __launch_bounds__(256)
void colsum_reduce(const float* __restrict__ skp, const float* __restrict__ svp,
                   float* __restrict__ sk, float* __restrict__ sv)
{
    const int i = blockIdx.x * 256 + threadIdx.x;
    float a = 0.f, c = 0.f;
    #pragma unroll 8
    for (int ch = 0; ch < SCH; ch++) {
        a += skp[(long)ch * Bsz * Dsz + i];
        c += svp[(long)ch * Bsz * Dsz + i];
    }
    sk[i] = a; sv[i] = c;
}

__global__ __launch_bounds__(128)
void matvec_kernel(const float* __restrict__ wk, const float* __restrict__ wv,
                   const float* __restrict__ sk, const float* __restrict__ sv,
                   float* __restrict__ wksk, float* __restrict__ wvsv)
{
    const int o = blockIdx.x, which = blockIdx.y, b = blockIdx.z;
    const float* W = which ? wv : wk;
    const float* s = (which ? sv : sk) + b * Dsz;
    float p = 0.f;
    for (int d = threadIdx.x; d < Dsz; d += 128) p += W[(long)o * Dsz + d] * s[d];
    #pragma unroll
    for (int off = 16; off; off >>= 1) p += __shfl_down_sync(0xffffffff, p, off);
    __shared__ float red[4];
    if ((threadIdx.x & 31) == 0) red[threadIdx.x >> 5] = p;
    __syncthreads();
    if (threadIdx.x == 0)
        (which ? wvsv : wksk)[b * Dsz + o] = red[0] + red[1] + red[2] + red[3];
}

// ---------------------------------------------------------------------------
#define PITCH 40
#define ARR_H (128 * PITCH)
#define STAGE_H (4 * ARR_H)
#define GSMEM (2 * STAGE_H * 2)

// Split-K GEMM: fp32 partials. grid (N/128, M/128, nbatch*2), z2 = 2z+kc.
__global__ __launch_bounds__(128)
void gemm_sk(const __nv_bfloat16* __restrict__ Agh, const __nv_bfloat16* __restrict__ Agl,
             const __nv_bfloat16* __restrict__ Bgh, const __nv_bfloat16* __restrict__ Bgl,
             float* __restrict__ Cp, int N, int Kc, int ldk, long sA, long sB)
{
    extern __shared__ __align__(16) __nv_bfloat16 smem[];
    const int z2 = blockIdx.z, z = z2 >> 1, kc = z2 & 1;
    const __nv_bfloat16* Azh = Agh + (long)z * sA + (long)kc * Kc;
    const __nv_bfloat16* Azl = Agl + (long)z * sA + (long)kc * Kc;
    const __nv_bfloat16* Bzh = Bgh + (long)z * sB + (long)kc * Kc;
    const __nv_bfloat16* Bzl = Bgl + (long)z * sB + (long)kc * Kc;
    const int bm = blockIdx.y * 128, bn = blockIdx.x * 128;
    const int tid = threadIdx.x, lane = tid & 31, warp = tid >> 5;
    const int wm = warp >> 1, wn = warp & 1;

    float acc[4][8][4];
    #pragma unroll
    for (int mt = 0; mt < 4; mt++)
        #pragma unroll
        for (int nt = 0; nt < 8; nt++)
            #pragma unroll
            for (int e = 0; e < 4; e++) acc[mt][nt][e] = 0.f;

    auto load_stage = [&](int buf, int k0) {
        __nv_bfloat16* S = smem + buf * STAGE_H;
        #pragma unroll
        for (int it = 0; it < 4; it++) {
            const int idx = tid + it * 128;
            const int r = idx >> 2, c = (idx & 3) * 8;
            const long ga = (long)(bm + r) * ldk + k0 + c;
            const long gb = (long)(bn + r) * ldk + k0 + c;
            __nv_bfloat16* row = S + r * PITCH + c;
            cpa16(row,             Azh + ga);
            cpa16(row + ARR_H,     Azl + ga);
            cpa16(row + 2 * ARR_H, Bzh + gb);
            cpa16(row + 3 * ARR_H, Bzl + gb);
        }
        cpa_commit();
    };

    load_stage(0, 0);
    load_stage(1, 32);

    const int NS = Kc / 32;
    for (int i = 0; i < NS; i++) {
        if (i == NS - 1) cpa_wait0(); else cpa_wait1();
        __syncthreads();

        const __nv_bfloat16* S = smem + (i & 1) * STAGE_H;
        const __nv_bfloat16* sAh = S;
        const __nv_bfloat16* sAl = S + ARR_H;
        const __nv_bfloat16* sBh = S + 2 * ARR_H;
        const __nv_bfloat16* sBl = S + 3 * ARR_H;

        #pragma unroll
        for (int kk = 0; kk < 32; kk += 16) {
            unsigned aH[4][4], aL[4][4];
            const int arow = wm * 64 + (lane & 15);
            const int acol = kk + (lane >> 4) * 8;
            #pragma unroll
            for (int mt = 0; mt < 4; mt++) {
                ldsm4(aH[mt], sAh + (arow + mt * 16) * PITCH + acol);
                ldsm4(aL[mt], sAl + (arow + mt * 16) * PITCH + acol);
            }
            const int g = lane >> 3;
            #pragma unroll
            for (int half = 0; half < 2; half++) {
                unsigned bH[4][2], bL[4][2];
                #pragma unroll
                for (int p = 0; p < 2; p++) {
                    const int brow = wn * 64 + half * 32 + p * 16 + ((g >> 1) << 3) + (lane & 7);
                    const int bcol = kk + (g & 1) * 8;
                    unsigned tt[4];
                    ldsm4(tt, sBh + brow * PITCH + bcol);
                    bH[2 * p][0] = tt[0]; bH[2 * p][1] = tt[1];
                    bH[2 * p + 1][0] = tt[2]; bH[2 * p + 1][1] = tt[3];
                    ldsm4(tt, sBl + brow * PITCH + bcol);
                    bL[2 * p][0] = tt[0]; bL[2 * p][1] = tt[1];
                    bL[2 * p + 1][0] = tt[2]; bL[2 * p + 1][1] = tt[3];
                }
                #pragma unroll
                for (int mt = 0; mt < 4; mt++)
                    #pragma unroll
                    for (int nn = 0; nn < 4; nn++) {
                        const int nt = half * 4 + nn;
                        mma_bf16(acc[mt][nt], aH[mt], bH[nn]);
                        mma_bf16(acc[mt][nt], aH[mt], bL[nn]);
                        mma_bf16(acc[mt][nt], aL[mt], bH[nn]);
                    }
            }
        }
        __syncthreads();
        if (i + 2 < NS) load_stage(i & 1, (i + 2) * 32);
    }

    float* Cz = Cp + (long)z2 * WELEM;
    const int crow = bm + wm * 64 + lane / 4;
    const int ccol0 = bn + wn * 64 + (lane % 4) * 2;
    #pragma unroll
    for (int mt = 0; mt < 4; mt++) {
        #pragma unroll
        for (int nt = 0; nt < 8; nt++) {
            const int col = ccol0 + nt * 8;
            const int r0 = crow + mt * 16;
            *(float2*)(Cz + (long)r0 * N + col) = make_float2(acc[mt][nt][0], acc[mt][nt][1]);
            *(float2*)(Cz + (long)(r0 + 8) * N + col) = make_float2(acc[mt][nt][2], acc[mt][nt][3]);
        }
    }
}

// Reduce split-K partials -> bf16 hi/lo
__global__ __launch_bounds__(256)
void sk_red_hl(const float* __restrict__ Cp, __nv_bfloat16* __restrict__ xh,
               __nv_bfloat16* __restrict__ xl)
{
    const int i = blockIdx.x * 256 + threadIdx.x;
    const int b = blockIdx.y;
    const float4 p0 = ((const float4*)(Cp + (long)(2 * b) * WELEM))[i];
    const float4 p1 = ((const float4*)(Cp + (long)(2 * b + 1) * WELEM))[i];
    const float s0 = p0.x + p1.x, s1 = p0.y + p1.y, s2 = p0.z + p1.z, s3 = p0.w + p1.w;
    __nv_bfloat16 h0 = __float2bfloat16_rn(s0), h1 = __float2bfloat16_rn(s1);
    __nv_bfloat16 h2 = __float2bfloat16_rn(s2), h3 = __float2bfloat16_rn(s3);
    const long o = (long)b * WELEM / 4 + i;
    ((__nv_bfloat162*)xh)[2 * o]     = __halves2bfloat162(h0, h1);
    ((__nv_bfloat162*)xh)[2 * o + 1] = __halves2bfloat162(h2, h3);
    ((__nv_bfloat162*)xl)[2 * o]     = __halves2bfloat162(
        __float2bfloat16_rn(s0 - __bfloat162float(h0)),
        __float2bfloat16_rn(s1 - __bfloat162float(h1)));
    ((__nv_bfloat162*)xl)[2 * o + 1] = __halves2bfloat162(
        __float2bfloat16_rn(s2 - __bfloat162float(h2)),
        __float2bfloat16_rn(s3 - __bfloat162float(h3)));
}

// ---------------------------------------------------------------------------
// Full-K GEMM with bias, fp32 out: grid (N/128, M/128, B)
// ---------------------------------------------------------------------------
__global__ __launch_bounds__(128)
void gemm_mma(const __nv_bfloat16* __restrict__ Agh, const __nv_bfloat16* __restrict__ Agl,
              const __nv_bfloat16* __restrict__ Bgh, const __nv_bfloat16* __restrict__ Bgl,
              const float* __restrict__ bias, float* __restrict__ Cf,
              int N, int K, long sA, long sB, long sC, long sBias)
{
    extern __shared__ __align__(16) __nv_bfloat16 smem[];
    const __nv_bfloat16* Azh = Agh + (long)blockIdx.z * sA;
    const __nv_bfloat16* Azl = Agl + (long)blockIdx.z * sA;
    const __nv_bfloat16* Bzh = Bgh + (long)blockIdx.z * sB;
    const __nv_bfloat16* Bzl = Bgl + (long)blockIdx.z * sB;
    const float* bz = bias + (long)blockIdx.z * sBias;
    const int bm = blockIdx.y * 128, bn = blockIdx.x * 128;
    const int tid = threadIdx.x, lane = tid & 31, warp = tid >> 5;
    const int wm = warp >> 1, wn = warp & 1;

    float acc[4][8][4];
    #pragma unroll
    for (int mt = 0; mt < 4; mt++)
        #pragma unroll
        for (int nt = 0; nt < 8; nt++)
            #pragma unroll
            for (int e = 0; e < 4; e++) acc[mt][nt][e] = 0.f;

    auto load_stage = [&](int buf, int k0) {
        __nv_bfloat16* S = smem + buf * STAGE_H;
        #pragma unroll
        for (int it = 0; it < 4; it++) {
            const int idx = tid + it * 128;
            const int r = idx >> 2, c = (idx & 3) * 8;
            const long ga = (long)(bm + r) * K + k0 + c;
            const long gb = (long)(bn + r) * K + k0 + c;
            __nv_bfloat16* row = S + r * PITCH + c;
            cpa16(row,             Azh + ga);
            cpa16(row + ARR_H,     Azl + ga);
            cpa16(row + 2 * ARR_H, Bzh + gb);
            cpa16(row + 3 * ARR_H, Bzl + gb);
        }
        cpa_commit();
    };

    load_stage(0, 0);
    load_stage(1, 32);

    const int NS = K / 32;
    for (int i = 0; i < NS; i++) {
        if (i == NS - 1) cpa_wait0(); else cpa_wait1();
        __syncthreads();

        const __nv_bfloat16* S = smem + (i & 1) * STAGE_H;
        const __nv_bfloat16* sAh = S;
        const __nv_bfloat16* sAl = S + ARR_H;
        const __nv_bfloat16* sBh = S + 2 * ARR_H;
        const __nv_bfloat16* sBl = S + 3 * ARR_H;

        #pragma unroll
        for (int kk = 0; kk < 32; kk += 16) {
            unsigned aH[4][4], aL[4][4];
            const int arow = wm * 64 + (lane & 15);
            const int acol = kk + (lane >> 4) * 8;
            #pragma unroll
            for (int mt = 0; mt < 4; mt++) {
                ldsm4(aH[mt], sAh + (arow + mt * 16) * PITCH + acol);
                ldsm4(aL[mt], sAl + (arow + mt * 16) * PITCH + acol);
            }
            const int g = lane >> 3;
            #pragma unroll
            for (int half = 0; half < 2; half++) {
                unsigned bH[4][2], bL[4][2];
                #pragma unroll
                for (int p = 0; p < 2; p++) {
                    const int brow = wn * 64 + half * 32 + p * 16 + ((g >> 1) << 3) + (lane & 7);
                    const int bcol = kk + (g & 1) * 8;
                    unsigned tt[4];
                    ldsm4(tt, sBh + brow * PITCH + bcol);
                    bH[2 * p][0] = tt[0]; bH[2 * p][1] = tt[1];
                    bH[2 * p + 1][0] = tt[2]; bH[2 * p + 1][1] = tt[3];
                    ldsm4(tt, sBl + brow * PITCH + bcol);
                    bL[2 * p][0] = tt[0]; bL[2 * p][1] = tt[1];
                    bL[2 * p + 1][0] = tt[2]; bL[2 * p + 1][1] = tt[3];
                }
                #pragma unroll
                for (int mt = 0; mt < 4; mt++)
                    #pragma unroll
                    for (int nn = 0; nn < 4; nn++) {
                        const int nt = half * 4 + nn;
                        mma_bf16(acc[mt][nt], aH[mt], bH[nn]);
                        mma_bf16(acc[mt][nt], aH[mt], bL[nn]);
                        mma_bf16(acc[mt][nt], aL[mt], bH[nn]);
                    }
            }
        }
        __syncthreads();
        if (i + 2 < NS) load_stage(i & 1, (i + 2) * 32);
    }

    float* Cz = Cf + (long)blockIdx.z * sC;
    const int crow = bm + wm * 64 + lane / 4;
    const int ccol0 = bn + wn * 64 + (lane % 4) * 2;
    #pragma unroll
    for (int mt = 0; mt < 4; mt++) {
        #pragma unroll
        for (int nt = 0; nt < 8; nt++) {
            const int col = ccol0 + nt * 8;
            const float2 bb = *(const float2*)(bz + col);
            const int r0 = crow + mt * 16;
            *(float2*)(Cz + (long)r0 * N + col) =
                make_float2(acc[mt][nt][0] + bb.x, acc[mt][nt][1] + bb.y);
            *(float2*)(Cz + (long)(r0 + 8) * N + col) =
                make_float2(acc[mt][nt][2] + bb.x, acc[mt][nt][3] + bb.y);
        }
    }
}

// ---------------------------------------------------------------------------
// mfold_part: reads Z split-K partials directly (Z = part[2b] + part[2b+1])
__global__ __launch_bounds__(256)
void mfold_part(const float* __restrict__ Cp, const float* __restrict__ wv,
                float* __restrict__ part)
{
    __shared__ float Zs[64][33];
    __shared__ float Ws[64][33];
    const int bh = blockIdx.x;
    const int b = bh >> 4, h = bh & 15;
    const int chunk = blockIdx.y;
    const int tid = threadIdx.x;
    const int ti = (tid >> 4) * 4, tj = (tid & 15) * 4;
    const float* Z0 = Cp + (long)(2 * b) * WELEM + (long)(h * DKsz) * Dsz;
    const float* Z1 = Cp + (long)(2 * b + 1) * WELEM + (long)(h * DKsz) * Dsz;
    const long wbase = (long)(h * DKsz) * Dsz;

    float acc[4][4] = {};
    for (int e0 = chunk * 256; e0 < chunk * 256 + 256; e0 += 32) {
        #pragma unroll
        for (int it = 0; it < 2; it++) {
            const int s = tid + it * 256;
            const int row = s >> 3, c4 = (s & 7) * 4;
            float4 z0 = *(const float4*)(Z0 + (long)row * Dsz + e0 + c4);
            float4 z1 = *(const float4*)(Z1 + (long)row * Dsz + e0 + c4);
            Zs[row][c4]   = z0.x + z1.x; Zs[row][c4+1] = z0.y + z1.y;
            Zs[row][c4+2] = z0.z + z1.z; Zs[row][c4+3] = z0.w + z1.w;
            float4 wvv = *(const float4*)(wv + wbase + (long)row * Dsz + e0 + c4);
            Ws[row][c4] = wvv.x; Ws[row][c4+1] = wvv.y; Ws[row][c4+2] = wvv.z; Ws[row][c4+3] = wvv.w;
        }
        __syncthreads();
        #pragma unroll
        for (int ee = 0; ee < 32; ee++) {
            float a[4], w[4];
            #pragma unroll
            for (int u = 0; u < 4; u++) { a[u] = Zs[ti + u][ee]; w[u] = Ws[tj + u][ee]; }
            #pragma unroll
            for (int i = 0; i < 4; i++)
                #pragma unroll
                for (int j = 0; j < 4; j++) acc[i][j] += a[i] * w[j];
        }
        __syncthreads();
    }
    float* outp = part + (long)chunk * MELEM + (long)bh * (DKsz * DKsz);
    #pragma unroll
    for (int i = 0; i < 4; i++)
        #pragma unroll
        for (int j = 0; j < 4; j++)
            outp[(ti + i) * DKsz + tj + j] = acc[i][j];
}

// wcomb with fused M-reduction: M built in smem from 4 Mpart chunks + bias terms.
__global__ __launch_bounds__(256)
void wcomb_kernel(const float* __restrict__ Mpart, const float* __restrict__ Wo,
                  const float* __restrict__ wksk, const float* __restrict__ wvsv,
                  const float* __restrict__ bk, const float* __restrict__ bv,
                  __nv_bfloat16* __restrict__ WTh, __nv_bfloat16* __restrict__ WTl)
{
    __shared__ float MshT[64 * 64];   // [j][i]
    __shared__ float WoSh[32][64];
    const int c0 = blockIdx.x * 32;
    const int h = blockIdx.y, b = blockIdx.z;
    const int tid = threadIdx.x;
    const long mbase = (long)(b * Hsz + h) * (DKsz * DKsz);

    for (int t = tid; t < 4096; t += 256) {
        const int i = t >> 6, j = t & 63;
        float s = 0.f;
        #pragma unroll
        for (int c = 0; c < 4; c++) s += Mpart[(long)c * MELEM + mbase + t];
        const int oi = h * DKsz + i, oj = h * DKsz + j;
        s += wksk[b * Dsz + oi] * bv[oj]
           + bk[oi] * wvsv[b * Dsz + oj]
           + (float)Ssz * bk[oi] * bv[oj];
        MshT[j * 64 + i] = s * 0.125f;
    }
    for (int t = tid; t < 2048; t += 256) {
        const int cc = t >> 6, j = t & 63;
        WoSh[cc][j] = Wo[(size_t)(c0 + cc) * Dsz + h * DKsz + j];
    }
    __syncthreads();

    const int cc = tid >> 3;
    const int i0 = (tid & 7) * 8;
    float acc[8] = {};
    #pragma unroll
    for (int j = 0; j < 64; j++) {
        const float w = WoSh[cc][j];
        #pragma unroll
        for (int u = 0; u < 8; u++) acc[u] += w * MshT[j * 64 + i0 + u];
    }
    const long off = (long)(b * Dsz + c0 + cc) * Dsz + h * DKsz + i0;
    #pragma unroll
    for (int u = 0; u < 8; u += 2) {
        __nv_bfloat16 h0 = __float2bfloat16_rn(acc[u]);
        __nv_bfloat16 h1 = __float2bfloat16_rn(acc[u + 1]);
        *(__nv_bfloat162*)(WTh + off + u) = __halves2bfloat162(h0, h1);
        *(__nv_bfloat162*)(WTl + off + u) = __halves2bfloat162(
            __float2bfloat16_rn(acc[u] - __bfloat162float(h0)),
            __float2bfloat16_rn(acc[u + 1] - __bfloat162float(h1)));
    }
}

__global__ __launch_bounds__(128)
void bprime_kernel(const __nv_bfloat16* __restrict__ WTh, const __nv_bfloat16* __restrict__ WTl,
                   const float* __restrict__ bq, const float* __restrict__ bo,
                   float* __restrict__ bp)
{
    const int c = blockIdx.x, b = blockIdx.y;
    const long base = (long)b * Dsz * Dsz + (long)c * Dsz;
    float p = 0.f;
    for (int o = threadIdx.x; o < Dsz; o += 128)
        p += bq[o] * (__bfloat162float(WTh[base + o]) + __bfloat162float(WTl[base + o]));
    #pragma unroll
    for (int off = 16; off; off >>= 1) p += __shfl_down_sync(0xffffffff, p, off);
    __shared__ float red[4];
    if ((threadIdx.x & 31) == 0) red[threadIdx.x >> 5] = p;
    __syncthreads();
    if (threadIdx.x == 0)
        bp[b * Dsz + c] = red[0] + red[1] + red[2] + red[3] + bo[c];
}

// ---------------------------------------------------------------------------
extern "C" void kernel_launch(void* const* d_in, const int* in_sizes, int n_in,
                              void* d_out, int out_size)
{
    const float* q  = (const float*)d_in[0];
    const float* k  = (const float*)d_in[1];
    const float* v  = (const float*)d_in[2];
    const float* wq = (const float*)d_in[3];
    const float* bq = (const float*)d_in[4];
    const float* wk = (const float*)d_in[5];
    const float* bk = (const float*)d_in[6];
    const float* wv = (const float*)d_in[7];
    const float* bv = (const float*)d_in[8];
    const float* wo = (const float*)d_in[9];
    const float* bo = (const float*)d_in[10];
    float* out = (float*)d_out;

    __nv_bfloat16 *qh, *ql, *kTh, *kTl, *vTh, *vTl, *wkh, *wkl, *wqTh, *wqTl;
    __nv_bfloat16 *Xh, *Xl, *WTh, *WTl, *Gh, *Gl;
    float *part, *skp, *svp, *sk, *sv, *wksk, *wvsv, *Mp, *bp;
    cudaGetSymbolAddress((void**)&qh, g_qh);     cudaGetSymbolAddress((void**)&ql, g_ql);
    cudaGetSymbolAddress((void**)&kTh, g_kTh);   cudaGetSymbolAddress((void**)&kTl, g_kTl);
    cudaGetSymbolAddress((void**)&vTh, g_vTh);   cudaGetSymbolAddress((void**)&vTl, g_vTl);
    cudaGetSymbolAddress((void**)&wkh, g_wkh);   cudaGetSymbolAddress((void**)&wkl, g_wkl);
    cudaGetSymbolAddress((void**)&wqTh, g_wqTh); cudaGetSymbolAddress((void**)&wqTl, g_wqTl);
    cudaGetSymbolAddress((void**)&Xh, g_Xh);     cudaGetSymbolAddress((void**)&Xl, g_Xl);
    cudaGetSymbolAddress((void**)&part, g_part);
    cudaGetSymbolAddress((void**)&skp, g_skpart); cudaGetSymbolAddress((void**)&svp, g_svpart);
    cudaGetSymbolAddress((void**)&sk, g_sk);     cudaGetSymbolAddress((void**)&sv, g_sv);
    cudaGetSymbolAddress((void**)&wksk, g_wksk); cudaGetSymbolAddress((void**)&wvsv, g_wvsv);
    cudaGetSymbolAddress((void**)&Mp, g_Mpart);
    cudaGetSymbolAddress((void**)&WTh, g_WTh);   cudaGetSymbolAddress((void**)&WTl, g_WTl);
    cudaGetSymbolAddress((void**)&Gh, g_Gh);     cudaGetSymbolAddress((void**)&Gl, g_Gl);
    cudaGetSymbolAddress((void**)&bp, g_bp);

    static cudaStream_t s1 = nullptr;
    static cudaEvent_t e0 = nullptr, e1 = nullptr, ewt = nullptr, ebp = nullptr;
    static int smem_set = 0;
    if (!smem_set) {
        cudaFuncSetAttribute(gemm_mma, cudaFuncAttributeMaxDynamicSharedMemorySize, GSMEM);
        cudaFuncSetAttribute(gemm_sk, cudaFuncAttributeMaxDynamicSharedMemorySize, GSMEM);
        cudaStreamCreateWithFlags(&s1, cudaStreamNonBlocking);
        cudaEventCreateWithFlags(&e0, cudaEventDisableTiming);
        cudaEventCreateWithFlags(&e1, cudaEventDisableTiming);
        cudaEventCreateWithFlags(&ewt, cudaEventDisableTiming);
        cudaEventCreateWithFlags(&ebp, cudaEventDisableTiming);
        smem_set = 1;
    }

    // ---- fork FIRST (exact R12/R14 structure & order) ----
    cudaEventRecord(e0, 0);
    cudaStreamWaitEvent(s1, e0, 0);
    split_kernel<<<NELEM / 4 / 256, 256, 0, s1>>>(q, qh, ql, NELEM / 4);
    split_kernel<<<WELEM / 4 / 256, 256, 0, s1>>>(wk, wkh, wkl, WELEM / 4);
    tsplit_kernel<<<dim3(Dsz / 32, Dsz / 32, 1), 256, 0, s1>>>(wq, wqTh, wqTl, Dsz, Dsz);
    colsum_part<<<dim3(Dsz / 256, SCH, Bsz), 256, 0, s1>>>(k, v, skp, svp);
    colsum_reduce<<<(Bsz * Dsz) / 256, 256, 0, s1>>>(skp, svp, sk, sv);
    matvec_kernel<<<dim3(Dsz, 2, Bsz), 128, 0, s1>>>(wk, wv, sk, sv, wksk, wvsv);
    cudaEventRecord(e1, s1);

    // ---- main chain ----
    tsplitKV<<<dim3(Dsz / 32, Ssz / 32, Bsz), 256>>>(k, v, kTh, kTl, vTh, vTl);

    // 1) X2_b = v_b^T k_b  split-K=2 -> bf16 h/l
    gemm_sk<<<dim3(8, 8, 2 * Bsz), 128, GSMEM>>>(
        vTh, vTl, kTh, kTl, part, Dsz, 1024, Ssz,
        (long)Dsz * Ssz, (long)Dsz * Ssz);
    sk_red_hl<<<dim3(WELEM / 4 / 256, Bsz), 256>>>(part, Xh, Xl);

    // join side stream
    cudaStreamWaitEvent(0, e1, 0);

    // 2) Z_b = Wk @ X2_b^T  split-K=2 -> fp32 partials
    gemm_sk<<<dim3(8, 8, 2 * Bsz), 128, GSMEM>>>(
        wkh, wkl, Xh, Xl, part, Dsz, 512, Dsz,
        0, (long)Dsz * Dsz);

    // 3) M chunk partials (reads Z partials directly)
    mfold_part<<<dim3(Bsz * Hsz, 4), 256>>>(part, wv, Mp);

    // 4) WT fold (fused M-reduce + bias corrections)
    wcomb_kernel<<<dim3(Dsz / 32, Hsz, Bsz), 256>>>(Mp, wo, wksk, wvsv, bk, bv, WTh, WTl);
    cudaEventRecord(ewt, 0);

    // bprime on side stream, parallel with G GEMM
    cudaStreamWaitEvent(s1, ewt, 0);
    bprime_kernel<<<dim3(Dsz, Bsz), 128, 0, s1>>>(WTh, WTl, bq, bo, bp);
    cudaEventRecord(ebp, s1);

    // 5) G_b = WT_b @ Wq  split-K=2 -> bf16 h/l
    gemm_sk<<<dim3(8, 8, 2 * Bsz), 128, GSMEM>>>(
        WTh, WTl, wqTh, wqTl, part, Dsz, 512, Dsz,
        (long)Dsz * Dsz, 0);
    sk_red_hl<<<dim3(WELEM / 4 / 256, Bsz), 256>>>(part, Gh, Gl);

    // join bprime
    cudaStreamWaitEvent(0, ebp, 0);

    // 6) out_b = q_b @ G_b^T + b'  (256 CTAs)
    gemm_mma<<<dim3(Dsz / 128, Ssz / 128, Bsz), 128, GSMEM>>>(
        qh, ql, Gh, Gl, bp, out,
        Dsz, Dsz, (long)Ssz * Dsz, (long)Dsz * Dsz, (long)Ssz * Dsz, Dsz);
}